// round 4
// baseline (speedup 1.0000x reference)
#include <cuda_runtime.h>
#include <math.h>

#define TT   1024
#define DM   1024
#define NQ   16
#define NKV  4
#define DH   64
#define NB   63
#define TOPN 8
#define WIN  256
#define SCALE 0.125f

// ---------------- scratch (device globals; no allocation) ----------------
__device__ float g_gates[TT * 48];
__device__ float g_kc[TT * 256];
__device__ float g_vc[TT * 256];
__device__ float g_ks[TT * 256];
__device__ float g_vs[TT * 256];
__device__ float g_kw[TT * 256];
__device__ float g_vw[TT * 256];
__device__ float g_ksum[NB * 256];
__device__ float g_vsum[NB * 256];
__device__ float g_outcmp[NQ * TT * DH];
__device__ float g_outslc[NQ * TT * DH];
__device__ int   g_sel[NKV * TT * TOPN];

// ---------------- generic 64x64 fp32 GEMM body: C[M,N] = A[M,K] @ B[N,K]^T ----------------
__device__ __forceinline__ void gemm64x64(const float* __restrict__ A,
                                          const float* __restrict__ B,
                                          float* __restrict__ C,
                                          int N, int K,
                                          const float* __restrict__ bias,
                                          int act_sigmoid)
{
    __shared__ float As[16][64];
    __shared__ float Bs[16][64];
    const int tid = threadIdx.x;           // 256 threads
    const int tx = tid & 15, ty = tid >> 4;
    const int m0 = blockIdx.y * 64, n0 = blockIdx.x * 64;
    const int lr = tid >> 2;               // 0..63
    const int lc = (tid & 3) << 2;         // 0,4,8,12
    float acc[4][4];
#pragma unroll
    for (int i = 0; i < 4; i++)
#pragma unroll
        for (int j = 0; j < 4; j++) acc[i][j] = 0.f;

    for (int k0 = 0; k0 < K; k0 += 16) {
        float4 av = *(const float4*)(A + (m0 + lr) * K + k0 + lc);
        float4 bv = make_float4(0.f, 0.f, 0.f, 0.f);
        int n = n0 + lr;
        if (n < N) bv = *(const float4*)(B + n * K + k0 + lc);
        As[lc + 0][lr] = av.x; As[lc + 1][lr] = av.y;
        As[lc + 2][lr] = av.z; As[lc + 3][lr] = av.w;
        Bs[lc + 0][lr] = bv.x; Bs[lc + 1][lr] = bv.y;
        Bs[lc + 2][lr] = bv.z; Bs[lc + 3][lr] = bv.w;
        __syncthreads();
#pragma unroll
        for (int kk = 0; kk < 16; kk++) {
            float a[4], b[4];
#pragma unroll
            for (int i = 0; i < 4; i++) a[i] = As[kk][ty * 4 + i];
#pragma unroll
            for (int j = 0; j < 4; j++) b[j] = Bs[kk][tx * 4 + j];
#pragma unroll
            for (int i = 0; i < 4; i++)
#pragma unroll
                for (int j = 0; j < 4; j++) acc[i][j] += a[i] * b[j];
        }
        __syncthreads();
    }
#pragma unroll
    for (int i = 0; i < 4; i++) {
        int m = m0 + ty * 4 + i;
#pragma unroll
        for (int j = 0; j < 4; j++) {
            int n = n0 + tx * 4 + j;
            if (n < N) {
                float v = acc[i][j];
                if (bias) v += bias[n];
                if (act_sigmoid) v = 1.f / (1.f + expf(-v));
                C[m * N + n] = v;
            }
        }
    }
}

__global__ void gates_kernel(const float* __restrict__ x,
                             const float* __restrict__ gw,
                             const float* __restrict__ gb)
{
    gemm64x64(x, gw, g_gates, 48, DM, gb, 1);
}

__global__ void proj6_kernel(const float* __restrict__ x,
                             const float* __restrict__ wkc, const float* __restrict__ wvc,
                             const float* __restrict__ wks, const float* __restrict__ wvs,
                             const float* __restrict__ wkw, const float* __restrict__ wvw)
{
    const float* B; float* C;
    switch (blockIdx.z) {
        case 0: B = wkc; C = g_kc; break;
        case 1: B = wvc; C = g_vc; break;
        case 2: B = wks; C = g_ks; break;
        case 3: B = wvs; C = g_vs; break;
        case 4: B = wkw; C = g_kw; break;
        default: B = wvw; C = g_vw; break;
    }
    gemm64x64(x, B, C, 256, DM, nullptr, 0);
}

// ---------------- block summaries: MLP(2048 -> 64 -> 64), exact gelu ----------------
// 256 threads: warp-per-8-outputs, lanes sweep j coalesced with float4.
__global__ void summarize_kernel(int isv,
                                 const float* __restrict__ bp,
                                 const float* __restrict__ w1, const float* __restrict__ b1,
                                 const float* __restrict__ w2, const float* __restrict__ b2)
{
    const float* src = isv ? g_vc : g_kc;
    float* dst = isv ? g_vsum : g_ksum;
    __shared__ float flat[2048];
    __shared__ float hid[64];
    const int n = blockIdx.x, kv = blockIdx.y, t0 = n * 16;
    const int tid = threadIdx.x, warp = tid >> 5, lane = tid & 31;

    for (int j = tid; j < 2048; j += 256) {
        int blk = j >> 6, d = j & 63;
        flat[j] = src[(t0 + blk) * 256 + kv * 64 + d] + bp[j];
    }
    __syncthreads();

    const float4* flat4 = (const float4*)flat;
#pragma unroll
    for (int oo = 0; oo < 8; oo++) {
        const int o = warp * 8 + oo;
        const float4* w4 = (const float4*)(w1 + o * 2048);
        float s = 0.f;
#pragma unroll
        for (int c = 0; c < 16; c++) {
            float4 wv = w4[lane + c * 32];
            float4 fv = flat4[lane + c * 32];
            s += wv.x * fv.x + wv.y * fv.y + wv.z * fv.z + wv.w * fv.w;
        }
        for (int off = 16; off; off >>= 1) s += __shfl_xor_sync(0xffffffffu, s, off);
        if (lane == 0) {
            s += b1[o];
            hid[o] = 0.5f * s * (1.f + erff(s * 0.7071067811865476f));  // exact gelu
        }
    }
    __syncthreads();

    if (tid < 64) {
        float s2 = b2[tid];
        const float* wo = w2 + tid * 64;
#pragma unroll
        for (int i = 0; i < 64; i++) s2 += hid[i] * wo[i];
        dst[n * 256 + kv * 64 + tid] = s2;
    }
}

// ---------------- compressed attention + importance + top-8 ----------------
__global__ void cmp_kernel(const float* __restrict__ q)
{
    const int t = blockIdx.x, kv = blockIdx.y;
    const int tid = threadIdx.x;            // 128 threads = 4 warps
    const int warp = tid >> 5, lane = tid & 31;
    __shared__ float4 qs4[4][16];
    __shared__ float p[4][64];
    __shared__ float impS[64];

    if (tid < 64) {
        int r = tid >> 4, c = tid & 15;
        qs4[r][c] = ((const float4*)(q + ((r * NKV + kv) * TT + t) * DH))[c];
    }
    __syncthreads();

    const int nvis = (t >= 31) ? (((t - 31) >> 4) + 1) : 0;  // fully-past blocks

    // warp = GQA head r; lane covers blocks n and n+32
    const int n0 = lane, n1 = lane + 32;
    float d0 = -1e30f, d1 = -1e30f;
    if (n0 < nvis) {
        const float4* kp4 = (const float4*)(g_ksum + n0 * 256 + kv * 64);
        float a = 0.f;
#pragma unroll
        for (int c = 0; c < 16; c++) {
            float4 kk = kp4[c]; float4 qq = qs4[warp][c];
            a += qq.x * kk.x + qq.y * kk.y + qq.z * kk.z + qq.w * kk.w;
        }
        d0 = a * SCALE;
    }
    if (n1 < NB && n1 < nvis) {
        const float4* kp4 = (const float4*)(g_ksum + n1 * 256 + kv * 64);
        float a = 0.f;
#pragma unroll
        for (int c = 0; c < 16; c++) {
            float4 kk = kp4[c]; float4 qq = qs4[warp][c];
            a += qq.x * kk.x + qq.y * kk.y + qq.z * kk.z + qq.w * kk.w;
        }
        d1 = a * SCALE;
    }
    if (nvis == 0) {
        // reference: softmax over all -1e30 -> uniform 1/63 (feeds top-k); out_cmp zeroed
        p[warp][n0] = 1.f / 63.f;
        if (n1 < NB) p[warp][n1] = 1.f / 63.f;
    } else {
        float m = fmaxf(d0, d1);
        for (int o = 16; o; o >>= 1) m = fmaxf(m, __shfl_xor_sync(0xffffffffu, m, o));
        float e0 = (n0 < nvis) ? expf(d0 - m) : 0.f;
        float e1 = (n1 < NB && n1 < nvis) ? expf(d1 - m) : 0.f;
        float s = e0 + e1;
        for (int o = 16; o; o >>= 1) s += __shfl_xor_sync(0xffffffffu, s, o);
        float inv = 1.f / s;
        p[warp][n0] = e0 * inv;
        if (n1 < NB) p[warp][n1] = e1 * inv;
    }
    __syncthreads();

    if (tid < NB) impS[tid] = p[0][tid] + p[1][tid] + p[2][tid] + p[3][tid];

    // out_cmp = p @ vsum (zero when nvis==0 since loop is empty)
    for (int i = tid; i < 256; i += 128) {
        int r = i >> 6, d = i & 63;
        float a = 0.f;
        for (int n = 0; n < nvis; n++) a += p[r][n] * g_vsum[n * 256 + kv * 64 + d];
        g_outcmp[((r * NKV + kv) * TT + t) * DH + d] = a;
    }
    __syncthreads();

    if (tid == 0) {
        unsigned long long used = 0ull;
        for (int i = 0; i < TOPN; i++) {
            float bv = -1.f; int bi = 0;
            for (int n = 0; n < NB; n++) {
                if (!((used >> n) & 1ull) && impS[n] > bv) { bv = impS[n]; bi = n; }
            }
            used |= 1ull << bi;
            g_sel[(kv * TT + t) * TOPN + i] = bi;
        }
    }
}

// ---------------- block-wide reductions (256 threads, 8 warps) ----------------
__device__ __forceinline__ float blk_max(float v, float* red, int warp, int lane)
{
    for (int o = 16; o; o >>= 1) v = fmaxf(v, __shfl_xor_sync(0xffffffffu, v, o));
    if (lane == 0) red[warp] = v;
    __syncthreads();
    float m = red[0];
#pragma unroll
    for (int w = 1; w < 8; w++) m = fmaxf(m, red[w]);
    __syncthreads();
    return m;
}
__device__ __forceinline__ float blk_sum(float v, float* red, int warp, int lane)
{
    for (int o = 16; o; o >>= 1) v += __shfl_xor_sync(0xffffffffu, v, o);
    if (lane == 0) red[warp] = v;
    __syncthreads();
    float s = red[0];
#pragma unroll
    for (int w = 1; w < 8; w++) s += red[w];
    __syncthreads();
    return s;
}

// ---------------- shared attention body: scores in sc[4][256], probs out ----------------
__device__ __forceinline__ void softmax4(float (&sc)[4][256], float* red, int tid, int warp, int lane)
{
#pragma unroll
    for (int r = 0; r < 4; r++) {
        float v = sc[r][tid];
        float m = blk_max(v, red, warp, lane);
        float e = expf(v - m);                 // -1e30 -> 0
        float s = blk_sum(e, red, warp, lane);
        sc[r][tid] = e / s;
        __syncthreads();
    }
}

// AV with single-pass V loads shared across the 4 GQA heads.
// threads: sub = tid>>4 handles s2 in [sub*16, sub*16+16), dq = tid&15 is the d-quad.
__device__ __forceinline__ void av_shared(const float* __restrict__ Vbase, int kv,
                                          const int* __restrict__ pos,
                                          const float (&sc)[4][256],
                                          float4 (&part)[4][16][17],
                                          int tid, float4 (&outv)[1], int* rout, int* dqout)
{
    const int sub = tid >> 4, dq = tid & 15;
    float4 a0 = make_float4(0,0,0,0), a1 = a0, a2 = a0, a3 = a0;
#pragma unroll 4
    for (int i = 0; i < 16; i++) {
        const int s2 = sub * 16 + i;
        const float4 vv = *(const float4*)(Vbase + pos[s2] * 256 + kv * 64 + dq * 4);
        float p0 = sc[0][s2], p1 = sc[1][s2], p2 = sc[2][s2], p3 = sc[3][s2];
        a0.x += p0 * vv.x; a0.y += p0 * vv.y; a0.z += p0 * vv.z; a0.w += p0 * vv.w;
        a1.x += p1 * vv.x; a1.y += p1 * vv.y; a1.z += p1 * vv.z; a1.w += p1 * vv.w;
        a2.x += p2 * vv.x; a2.y += p2 * vv.y; a2.z += p2 * vv.z; a2.w += p2 * vv.w;
        a3.x += p3 * vv.x; a3.y += p3 * vv.y; a3.z += p3 * vv.z; a3.w += p3 * vv.w;
    }
    part[0][sub][dq] = a0; part[1][sub][dq] = a1;
    part[2][sub][dq] = a2; part[3][sub][dq] = a3;
    __syncthreads();
    if (tid < 64) {
        const int r = tid >> 4, dq2 = tid & 15;
        float4 s = make_float4(0,0,0,0);
#pragma unroll
        for (int u = 0; u < 16; u++) {
            float4 p = part[r][u][dq2];
            s.x += p.x; s.y += p.y; s.z += p.z; s.w += p.w;
        }
        outv[0] = s; *rout = r; *dqout = dq2;
    }
}

// ---------------- selected-blocks attention ----------------
__global__ void slc_kernel(const float* __restrict__ q)
{
    const int t = blockIdx.x, kv = blockIdx.y, tid = threadIdx.x;  // 256 threads
    const int warp = tid >> 5, lane = tid & 31;
    __shared__ float4 qs4[4][16];
    __shared__ float sc[4][256];
    __shared__ int   pos[256];
    __shared__ float red[8];
    __shared__ float4 part[4][16][17];

    if (tid < 64) {
        int r = tid >> 4, c = tid & 15;
        qs4[r][c] = ((const float4*)(q + ((r * NKV + kv) * TT + t) * DH))[c];
    }
    {
        int blk = g_sel[(kv * TT + t) * TOPN + (tid >> 5)];
        pos[tid] = blk * 16 + (tid & 31);    // starts[blk] + offset (always < T)
    }
    __syncthreads();

    const int ps = pos[tid];
    const bool valid = (ps <= t);
    float acc[4] = {0.f, 0.f, 0.f, 0.f};
    if (valid) {
        const float4* kp4 = (const float4*)(g_ks + ps * 256 + kv * 64);
#pragma unroll
        for (int c = 0; c < 16; c++) {
            float4 kk = kp4[c];
#pragma unroll
            for (int r = 0; r < 4; r++) {
                float4 qq = qs4[r][c];
                acc[r] += qq.x * kk.x + qq.y * kk.y + qq.z * kk.z + qq.w * kk.w;
            }
        }
    }
#pragma unroll
    for (int r = 0; r < 4; r++) sc[r][tid] = valid ? acc[r] * SCALE : -1e30f;
    __syncthreads();

    softmax4(sc, red, tid, warp, lane);

    float4 outv[1]; int r, dq;
    av_shared(g_vs, kv, pos, sc, part, tid, outv, &r, &dq);
    if (tid < 64)
        ((float4*)(g_outslc + ((r * NKV + kv) * TT + t) * DH))[dq] = outv[0];
}

// ---------------- sliding window attention + gating + final output ----------------
__global__ void win_final_kernel(const float* __restrict__ q, float* __restrict__ out)
{
    const int t = blockIdx.x, kv = blockIdx.y, tid = threadIdx.x;  // 256 threads
    const int warp = tid >> 5, lane = tid & 31;
    __shared__ float4 qs4[4][16];
    __shared__ float sc[4][256];
    __shared__ int   pos[256];
    __shared__ float red[8];
    __shared__ float4 part[4][16][17];

    const int j0 = (t >= WIN - 1) ? t - (WIN - 1) : 0;
    const int nj = t - j0 + 1;

    if (tid < 64) {
        int r = tid >> 4, c = tid & 15;
        qs4[r][c] = ((const float4*)(q + ((r * NKV + kv) * TT + t) * DH))[c];
    }
    pos[tid] = j0 + tid;                    // always < T
    __syncthreads();

    const bool valid = (tid < nj);
    float acc[4] = {0.f, 0.f, 0.f, 0.f};
    if (valid) {
        const float4* kp4 = (const float4*)(g_kw + pos[tid] * 256 + kv * 64);
#pragma unroll
        for (int c = 0; c < 16; c++) {
            float4 kk = kp4[c];
#pragma unroll
            for (int r = 0; r < 4; r++) {
                float4 qq = qs4[r][c];
                acc[r] += qq.x * kk.x + qq.y * kk.y + qq.z * kk.z + qq.w * kk.w;
            }
        }
    }
#pragma unroll
    for (int r = 0; r < 4; r++) sc[r][tid] = valid ? acc[r] * SCALE : -1e30f;
    __syncthreads();

    softmax4(sc, red, tid, warp, lane);

    float4 outv[1]; int r, dq;
    av_shared(g_vw, kv, pos, sc, part, tid, outv, &r, &dq);

    if (tid < 64) {
        const int h = r * NKV + kv;
        const float g0 = g_gates[t * 48 + h * 3 + 0];
        const float g1 = g_gates[t * 48 + h * 3 + 1];
        const float g2 = g_gates[t * 48 + h * 3 + 2];
        const int obase = (h * TT + t) * DH;
        float4 oc = ((const float4*)(g_outcmp + obase))[dq];
        float4 os = ((const float4*)(g_outslc + obase))[dq];
        float4 res;
        res.x = g0 * oc.x + g1 * os.x + g2 * outv[0].x;
        res.y = g0 * oc.y + g1 * os.y + g2 * outv[0].y;
        res.z = g0 * oc.z + g1 * os.z + g2 * outv[0].z;
        res.w = g0 * oc.w + g1 * os.w + g2 * outv[0].w;
        ((float4*)(out + obase))[dq] = res;
    }
}

// ---------------- launch ----------------
extern "C" void kernel_launch(void* const* d_in, const int* in_sizes, int n_in,
                              void* d_out, int out_size)
{
    (void)in_sizes; (void)n_in; (void)out_size;
    const float* x       = (const float*)d_in[0];
    const float* q       = (const float*)d_in[1];
    const float* gate_w  = (const float*)d_in[2];
    const float* gate_b  = (const float*)d_in[3];
    const float* wk_cmp  = (const float*)d_in[4];
    const float* wv_cmp  = (const float*)d_in[5];
    const float* wk_slc  = (const float*)d_in[6];
    const float* wv_slc  = (const float*)d_in[7];
    const float* wk_win  = (const float*)d_in[8];
    const float* wv_win  = (const float*)d_in[9];
    const float* blockp  = (const float*)d_in[10];
    const float* ck1_w   = (const float*)d_in[11];
    const float* ck1_b   = (const float*)d_in[12];
    const float* ck2_w   = (const float*)d_in[13];
    const float* ck2_b   = (const float*)d_in[14];
    const float* cv1_w   = (const float*)d_in[15];
    const float* cv1_b   = (const float*)d_in[16];
    const float* cv2_w   = (const float*)d_in[17];
    const float* cv2_b   = (const float*)d_in[18];
    float* out = (float*)d_out;

    gates_kernel<<<dim3(1, 16), 256>>>(x, gate_w, gate_b);
    proj6_kernel<<<dim3(4, 16, 6), 256>>>(x, wk_cmp, wv_cmp, wk_slc, wv_slc, wk_win, wv_win);
    summarize_kernel<<<dim3(NB, NKV), 256>>>(0, blockp, ck1_w, ck1_b, ck2_w, ck2_b);
    summarize_kernel<<<dim3(NB, NKV), 256>>>(1, blockp, cv1_w, cv1_b, cv2_w, cv2_b);
    cmp_kernel<<<dim3(TT, NKV), 128>>>(q);
    slc_kernel<<<dim3(TT, NKV), 256>>>(q);
    win_final_kernel<<<dim3(TT, NKV), 256>>>(q, out);
}

// round 5
// speedup vs baseline: 1.2970x; 1.2970x over previous
#include <cuda_runtime.h>
#include <math.h>

#define TT   1024
#define DM   1024
#define NQ   16
#define NKV  4
#define DH   64
#define NB   63
#define TOPN 8
#define WIN  256
#define SCALE 0.125f

typedef unsigned long long ull;

// packed fp32x2 FMA: d = a*b + d  (per 32-bit half) -> SASS FFMA2
#define FMA2(d, a, b)  asm("fma.rn.f32x2 %0, %1, %2, %0;" : "+l"(d) : "l"(a), "l"(b))
// duplicate one float into both halves of a b64
#define PACKDUP(d, a)  asm("mov.b64 %0, {%1, %1};" : "=l"(d) : "f"(a))

// ---------------- scratch (device globals; no allocation) ----------------
__device__ float g_gates[TT * 48];
__device__ float g_kc[TT * 256];
__device__ float g_vc[TT * 256];
__device__ float g_ks[TT * 256];
__device__ float g_vs[TT * 256];
__device__ float g_kw[TT * 256];
__device__ float g_vw[TT * 256];
__device__ float g_ksum[NB * 256];
__device__ float g_vsum[NB * 256];
__device__ float g_outcmp[NQ * TT * DH];
__device__ float g_outslc[NQ * TT * DH];
__device__ int   g_sel[NKV * TT * TOPN];

// ================= fused GEMM: 6 projections + gates, f32x2, 8x8 microtile =================
// 64 threads, 64x64 tile. blocks 0..383: proj (tensor=b>>6, rem: mtile=rem>>2, ntile=rem&3)
// blocks 384..399: gates (N=48, bias+sigmoid).
__global__ __launch_bounds__(64) void gemm_all_kernel(
    const float* __restrict__ x,
    const float* __restrict__ gate_w, const float* __restrict__ gate_b,
    const float* __restrict__ wkc, const float* __restrict__ wvc,
    const float* __restrict__ wks, const float* __restrict__ wvs,
    const float* __restrict__ wkw, const float* __restrict__ wvw)
{
    __shared__ float As[16][64];
    __shared__ float Bs[16][64];

    const int b = blockIdx.x;
    const float* Bw;
    float* C;
    int Nn, ldc, m0, n0;
    bool gate = false;
    if (b < 384) {
        const int tz = b >> 6, rem = b & 63;
        switch (tz) {
            case 0: Bw = wkc; C = g_kc; break;
            case 1: Bw = wvc; C = g_vc; break;
            case 2: Bw = wks; C = g_ks; break;
            case 3: Bw = wvs; C = g_vs; break;
            case 4: Bw = wkw; C = g_kw; break;
            default: Bw = wvw; C = g_vw; break;
        }
        m0 = (rem >> 2) * 64; n0 = (rem & 3) * 64; Nn = 256; ldc = 256;
    } else {
        Bw = gate_w; C = g_gates;
        m0 = (b - 384) * 64; n0 = 0; Nn = 48; ldc = 48; gate = true;
    }

    const int tid = threadIdx.x;
    const int tx = tid & 7, ty = tid >> 3;     // 8x8 thread grid
    const int lr = tid >> 2, lc4 = (tid & 3) << 2;

    ull acc[8][4];
#pragma unroll
    for (int i = 0; i < 8; i++)
#pragma unroll
        for (int j = 0; j < 4; j++) acc[i][j] = 0ull;

    for (int k0 = 0; k0 < DM; k0 += 16) {
#pragma unroll
        for (int p = 0; p < 4; p++) {
            const int row = lr + p * 16;
            float4 av = *(const float4*)(x + (m0 + row) * DM + k0 + lc4);
            As[lc4 + 0][row] = av.x; As[lc4 + 1][row] = av.y;
            As[lc4 + 2][row] = av.z; As[lc4 + 3][row] = av.w;
            float4 bv = make_float4(0.f, 0.f, 0.f, 0.f);
            const int n = n0 + row;
            if (n < Nn) bv = *(const float4*)(Bw + n * DM + k0 + lc4);
            Bs[lc4 + 0][row] = bv.x; Bs[lc4 + 1][row] = bv.y;
            Bs[lc4 + 2][row] = bv.z; Bs[lc4 + 3][row] = bv.w;
        }
        __syncthreads();
#pragma unroll
        for (int kk = 0; kk < 16; kk++) {
            float a8[8];
            *(float4*)(a8 + 0) = *(const float4*)&As[kk][ty * 8];
            *(float4*)(a8 + 4) = *(const float4*)&As[kk][ty * 8 + 4];
            ull b4[4];
#pragma unroll
            for (int j = 0; j < 4; j++) b4[j] = *(const ull*)&Bs[kk][tx * 8 + 2 * j];
#pragma unroll
            for (int i = 0; i < 8; i++) {
                ull aa; PACKDUP(aa, a8[i]);
#pragma unroll
                for (int j = 0; j < 4; j++) FMA2(acc[i][j], aa, b4[j]);
            }
        }
        __syncthreads();
    }

#pragma unroll
    for (int i = 0; i < 8; i++) {
        const int m = m0 + ty * 8 + i;
#pragma unroll
        for (int j = 0; j < 4; j++) {
            const int n = n0 + tx * 8 + 2 * j;
            if (n < Nn) {
                union { ull u; float2 f; } cv; cv.u = acc[i][j];
                float vx = cv.f.x, vy = cv.f.y;
                if (gate) {
                    vx += gate_b[n];     vy += gate_b[n + 1];
                    vx = 1.f / (1.f + expf(-vx));
                    vy = 1.f / (1.f + expf(-vy));
                }
                *(float2*)(C + m * ldc + n) = make_float2(vx, vy);
            }
        }
    }
}

// ================= block summaries: MLP(2048->64->64), k+v fused, kv-reuse =================
// grid (63, 2): y=0 k-path, y=1 v-path. 512 threads. Each block does all 4 kv heads,
// reading w1 (512KB) exactly once and reusing each load across 4 outputs x 4 kv.
__global__ __launch_bounds__(512) void summarize_kernel(
    const float* __restrict__ bp,
    const float* __restrict__ ck1w, const float* __restrict__ ck1b,
    const float* __restrict__ ck2w, const float* __restrict__ ck2b,
    const float* __restrict__ cv1w, const float* __restrict__ cv1b,
    const float* __restrict__ cv2w, const float* __restrict__ cv2b)
{
    const int n = blockIdx.x, path = blockIdx.y;
    const float* src = path ? g_vc : g_kc;
    float* dst       = path ? g_vsum : g_ksum;
    const float* w1  = path ? cv1w : ck1w;
    const float* b1  = path ? cv1b : ck1b;
    const float* w2  = path ? cv2w : ck2w;
    const float* b2  = path ? cv2b : ck2b;

    __shared__ float flat[4][2048];
    __shared__ float hid[4][64];
    const int tid = threadIdx.x, warp = tid >> 5, lane = tid & 31;
    const int t0 = n * 16;

    for (int idx = tid; idx < 8192; idx += 512) {
        const int t = idx >> 8, c = idx & 255;
        flat[c >> 6][t * 64 + (c & 63)] = src[(t0 + t) * 256 + c] + bp[t * 64 + (c & 63)];
    }
    __syncthreads();

    // warp w computes outputs o = 4w..4w+3 for all 4 kv heads
    float s[4][4];
#pragma unroll
    for (int oo = 0; oo < 4; oo++)
#pragma unroll
        for (int kv = 0; kv < 4; kv++) s[oo][kv] = 0.f;

    const float4* w1r0 = (const float4*)(w1 + (warp * 4 + 0) * 2048);
    const float4* w1r1 = (const float4*)(w1 + (warp * 4 + 1) * 2048);
    const float4* w1r2 = (const float4*)(w1 + (warp * 4 + 2) * 2048);
    const float4* w1r3 = (const float4*)(w1 + (warp * 4 + 3) * 2048);

#pragma unroll 4
    for (int c = 0; c < 16; c++) {
        const int off = lane + c * 32;
        float4 wv[4];
        wv[0] = w1r0[off]; wv[1] = w1r1[off]; wv[2] = w1r2[off]; wv[3] = w1r3[off];
#pragma unroll
        for (int kv = 0; kv < 4; kv++) {
            const float4 fv = ((const float4*)flat[kv])[off];
#pragma unroll
            for (int oo = 0; oo < 4; oo++)
                s[oo][kv] += wv[oo].x * fv.x + wv[oo].y * fv.y + wv[oo].z * fv.z + wv[oo].w * fv.w;
        }
    }
#pragma unroll
    for (int oo = 0; oo < 4; oo++)
#pragma unroll
        for (int kv = 0; kv < 4; kv++)
            for (int off = 16; off; off >>= 1)
                s[oo][kv] += __shfl_xor_sync(0xffffffffu, s[oo][kv], off);

    if (lane == 0) {
#pragma unroll
        for (int oo = 0; oo < 4; oo++) {
            const int o = warp * 4 + oo;
#pragma unroll
            for (int kv = 0; kv < 4; kv++) {
                float g = s[oo][kv] + b1[o];
                hid[kv][o] = 0.5f * g * (1.f + erff(g * 0.7071067811865476f));  // exact gelu
            }
        }
    }
    __syncthreads();

    if (tid < 256) {
        const int kv = tid >> 6, o = tid & 63;
        const float4* w2r = (const float4*)(w2 + o * 64);
        const float4* h4  = (const float4*)hid[kv];
        float s2 = b2[o];
#pragma unroll
        for (int c = 0; c < 16; c++) {
            float4 wv = w2r[c], hv = h4[c];
            s2 += wv.x * hv.x + wv.y * hv.y + wv.z * hv.z + wv.w * hv.w;
        }
        dst[n * 256 + kv * 64 + o] = s2;
    }
}

// ================= compressed attention + importance + warp-parallel top-8 =================
__global__ __launch_bounds__(128) void cmp_kernel(const float* __restrict__ q)
{
    const int t = blockIdx.x, kv = blockIdx.y;
    const int tid = threadIdx.x;            // 128 threads = 4 warps
    const int warp = tid >> 5, lane = tid & 31;
    __shared__ float4 qs4[4][16];
    __shared__ float p[4][64];
    __shared__ float impS[64];

    if (tid < 64) {
        int r = tid >> 4, c = tid & 15;
        qs4[r][c] = ((const float4*)(q + ((r * NKV + kv) * TT + t) * DH))[c];
    }
    __syncthreads();

    const int nvis = (t >= 31) ? (((t - 31) >> 4) + 1) : 0;  // fully-past blocks

    const int n0 = lane, n1 = lane + 32;
    float d0 = -1e30f, d1 = -1e30f;
    if (n0 < nvis) {
        const float4* kp4 = (const float4*)(g_ksum + n0 * 256 + kv * 64);
        float a = 0.f;
#pragma unroll
        for (int c = 0; c < 16; c++) {
            float4 kk = kp4[c]; float4 qq = qs4[warp][c];
            a += qq.x * kk.x + qq.y * kk.y + qq.z * kk.z + qq.w * kk.w;
        }
        d0 = a * SCALE;
    }
    if (n1 < NB && n1 < nvis) {
        const float4* kp4 = (const float4*)(g_ksum + n1 * 256 + kv * 64);
        float a = 0.f;
#pragma unroll
        for (int c = 0; c < 16; c++) {
            float4 kk = kp4[c]; float4 qq = qs4[warp][c];
            a += qq.x * kk.x + qq.y * kk.y + qq.z * kk.z + qq.w * kk.w;
        }
        d1 = a * SCALE;
    }
    if (nvis == 0) {
        p[warp][n0] = 1.f / 63.f;
        if (n1 < NB) p[warp][n1] = 1.f / 63.f;
    } else {
        float m = fmaxf(d0, d1);
        for (int o = 16; o; o >>= 1) m = fmaxf(m, __shfl_xor_sync(0xffffffffu, m, o));
        float e0 = (n0 < nvis) ? expf(d0 - m) : 0.f;
        float e1 = (n1 < NB && n1 < nvis) ? expf(d1 - m) : 0.f;
        float s = e0 + e1;
        for (int o = 16; o; o >>= 1) s += __shfl_xor_sync(0xffffffffu, s, o);
        float inv = 1.f / s;
        p[warp][n0] = e0 * inv;
        if (n1 < NB) p[warp][n1] = e1 * inv;
    }
    __syncthreads();

    if (tid < NB) impS[tid] = p[0][tid] + p[1][tid] + p[2][tid] + p[3][tid];

    // out_cmp = p @ vsum (zero when nvis==0)
    for (int i = tid; i < 256; i += 128) {
        int r = i >> 6, d = i & 63;
        float a = 0.f;
        for (int nn = 0; nn < nvis; nn++) a += p[r][nn] * g_vsum[nn * 256 + kv * 64 + d];
        g_outcmp[((r * NKV + kv) * TT + t) * DH + d] = a;
    }
    __syncthreads();

    // warp-parallel top-8: argmax with lowest-index tie-break == serial strict-> scan
    if (warp == 0) {
        float v0 = (n0 < NB) ? impS[n0] : -2.f;
        float v1 = (n1 < NB) ? impS[n1] : -2.f;
#pragma unroll
        for (int it = 0; it < TOPN; it++) {
            float cv = v0; int ci = n0;
            if (v1 > cv) { cv = v1; ci = n1; }      // tie keeps lower index n0
            for (int off = 16; off; off >>= 1) {
                float ov = __shfl_xor_sync(0xffffffffu, cv, off);
                int   oi = __shfl_xor_sync(0xffffffffu, ci, off);
                if (ov > cv || (ov == cv && oi < ci)) { cv = ov; ci = oi; }
            }
            if (lane == 0) g_sel[(kv * TT + t) * TOPN + it] = ci;
            if (n0 == ci) v0 = -2.f;
            if (n1 == ci) v1 = -2.f;
        }
    }
}

// ================= 3-barrier softmax over sc rows (thread = position, 4 heads) ===============
__device__ __forceinline__ void softmax4_fast(float (&val)[4], float (&sc)[4][256],
                                              float (&redm)[4][8], float (&reds)[4][8],
                                              int tid, int warp, int lane)
{
#pragma unroll
    for (int r = 0; r < 4; r++) {
        float m = val[r];
        for (int o = 16; o; o >>= 1) m = fmaxf(m, __shfl_xor_sync(0xffffffffu, m, o));
        if (lane == 0) redm[r][warp] = m;
    }
    __syncthreads();
    float e[4];
#pragma unroll
    for (int r = 0; r < 4; r++) {
        float m = redm[r][0];
#pragma unroll
        for (int w = 1; w < 8; w++) m = fmaxf(m, redm[r][w]);
        e[r] = expf(val[r] - m);
        float s = e[r];
        for (int o = 16; o; o >>= 1) s += __shfl_xor_sync(0xffffffffu, s, o);
        if (lane == 0) reds[r][warp] = s;
    }
    __syncthreads();
#pragma unroll
    for (int r = 0; r < 4; r++) {
        float s = reds[r][0];
#pragma unroll
        for (int w = 1; w < 8; w++) s += reds[r][w];
        sc[r][tid] = e[r] / s;
    }
    __syncthreads();
}

// ================= selected-blocks attention =================
__global__ __launch_bounds__(256) void slc_kernel(const float* __restrict__ q)
{
    const int t = blockIdx.x, kv = blockIdx.y, tid = threadIdx.x;
    const int warp = tid >> 5, lane = tid & 31;
    __shared__ float4 qs4[4][16];
    __shared__ float sc[4][256];
    __shared__ int   pos[256];
    __shared__ float redm[4][8], reds[4][8];
    __shared__ float4 part[4][16][17];

    if (tid < 64) {
        int r = tid >> 4, c = tid & 15;
        qs4[r][c] = ((const float4*)(q + ((r * NKV + kv) * TT + t) * DH))[c];
    }
    {
        int blk = g_sel[(kv * TT + t) * TOPN + (tid >> 5)];
        pos[tid] = blk * 16 + (tid & 31);    // starts[blk] + offset, always < T
    }
    __syncthreads();

    const int ps = pos[tid];
    const bool valid = (ps <= t);
    float val[4];
    if (valid) {
        const float4* kp4 = (const float4*)(g_ks + ps * 256 + kv * 64);
        float acc[4] = {0.f, 0.f, 0.f, 0.f};
#pragma unroll
        for (int c = 0; c < 16; c++) {
            float4 kk = kp4[c];
#pragma unroll
            for (int r = 0; r < 4; r++) {
                float4 qq = qs4[r][c];
                acc[r] += qq.x * kk.x + qq.y * kk.y + qq.z * kk.z + qq.w * kk.w;
            }
        }
#pragma unroll
        for (int r = 0; r < 4; r++) val[r] = acc[r] * SCALE;
    } else {
#pragma unroll
        for (int r = 0; r < 4; r++) val[r] = -1e30f;
    }

    softmax4_fast(val, sc, redm, reds, tid, warp, lane);

    // AV: sub covers 16 positions, dq is the d-quad; V loaded once, shared by 4 heads
    const int sub = tid >> 4, dq = tid & 15;
    float4 a0 = make_float4(0,0,0,0), a1 = a0, a2 = a0, a3 = a0;
#pragma unroll 4
    for (int i = 0; i < 16; i++) {
        const int s2 = sub * 16 + i;
        const float4 vv = *(const float4*)(g_vs + pos[s2] * 256 + kv * 64 + dq * 4);
        float p0 = sc[0][s2], p1 = sc[1][s2], p2 = sc[2][s2], p3 = sc[3][s2];
        a0.x += p0 * vv.x; a0.y += p0 * vv.y; a0.z += p0 * vv.z; a0.w += p0 * vv.w;
        a1.x += p1 * vv.x; a1.y += p1 * vv.y; a1.z += p1 * vv.z; a1.w += p1 * vv.w;
        a2.x += p2 * vv.x; a2.y += p2 * vv.y; a2.z += p2 * vv.z; a2.w += p2 * vv.w;
        a3.x += p3 * vv.x; a3.y += p3 * vv.y; a3.z += p3 * vv.z; a3.w += p3 * vv.w;
    }
    part[0][sub][dq] = a0; part[1][sub][dq] = a1;
    part[2][sub][dq] = a2; part[3][sub][dq] = a3;
    __syncthreads();
    if (tid < 64) {
        const int r = tid >> 4, dq2 = tid & 15;
        float4 s = make_float4(0,0,0,0);
#pragma unroll
        for (int u = 0; u < 16; u++) {
            float4 pv = part[r][u][dq2];
            s.x += pv.x; s.y += pv.y; s.z += pv.z; s.w += pv.w;
        }
        ((float4*)(g_outslc + ((r * NKV + kv) * TT + t) * DH))[dq2] = s;
    }
}

// ================= sliding window attention + gating + final output =================
__global__ __launch_bounds__(256) void win_final_kernel(const float* __restrict__ q,
                                                        float* __restrict__ out)
{
    const int t = blockIdx.x, kv = blockIdx.y, tid = threadIdx.x;
    const int warp = tid >> 5, lane = tid & 31;
    __shared__ float4 qs4[4][16];
    __shared__ float sc[4][256];
    __shared__ float redm[4][8], reds[4][8];
    __shared__ float4 part[4][16][17];

    const int j0 = (t >= WIN - 1) ? t - (WIN - 1) : 0;
    const int nj = t - j0 + 1;

    if (tid < 64) {
        int r = tid >> 4, c = tid & 15;
        qs4[r][c] = ((const float4*)(q + ((r * NKV + kv) * TT + t) * DH))[c];
    }
    __syncthreads();

    const bool valid = (tid < nj);
    float val[4];
    if (valid) {
        const float4* kp4 = (const float4*)(g_kw + (j0 + tid) * 256 + kv * 64);
        float acc[4] = {0.f, 0.f, 0.f, 0.f};
#pragma unroll
        for (int c = 0; c < 16; c++) {
            float4 kk = kp4[c];
#pragma unroll
            for (int r = 0; r < 4; r++) {
                float4 qq = qs4[r][c];
                acc[r] += qq.x * kk.x + qq.y * kk.y + qq.z * kk.z + qq.w * kk.w;
            }
        }
#pragma unroll
        for (int r = 0; r < 4; r++) val[r] = acc[r] * SCALE;
    } else {
#pragma unroll
        for (int r = 0; r < 4; r++) val[r] = -1e30f;
    }

    softmax4_fast(val, sc, redm, reds, tid, warp, lane);

    const int sub = tid >> 4, dq = tid & 15;
    float4 a0 = make_float4(0,0,0,0), a1 = a0, a2 = a0, a3 = a0;
#pragma unroll 4
    for (int i = 0; i < 16; i++) {
        const int s2 = sub * 16 + i;
        const float4 vv = *(const float4*)(g_vw + (j0 + s2) * 256 + kv * 64 + dq * 4);
        float p0 = sc[0][s2], p1 = sc[1][s2], p2 = sc[2][s2], p3 = sc[3][s2];
        a0.x += p0 * vv.x; a0.y += p0 * vv.y; a0.z += p0 * vv.z; a0.w += p0 * vv.w;
        a1.x += p1 * vv.x; a1.y += p1 * vv.y; a1.z += p1 * vv.z; a1.w += p1 * vv.w;
        a2.x += p2 * vv.x; a2.y += p2 * vv.y; a2.z += p2 * vv.z; a2.w += p2 * vv.w;
        a3.x += p3 * vv.x; a3.y += p3 * vv.y; a3.z += p3 * vv.z; a3.w += p3 * vv.w;
    }
    part[0][sub][dq] = a0; part[1][sub][dq] = a1;
    part[2][sub][dq] = a2; part[3][sub][dq] = a3;
    __syncthreads();
    if (tid < 64) {
        const int r = tid >> 4, dq2 = tid & 15;
        float4 s = make_float4(0,0,0,0);
#pragma unroll
        for (int u = 0; u < 16; u++) {
            float4 pv = part[r][u][dq2];
            s.x += pv.x; s.y += pv.y; s.z += pv.z; s.w += pv.w;
        }
        const int h = r * NKV + kv;
        const float g0 = g_gates[t * 48 + h * 3 + 0];
        const float g1 = g_gates[t * 48 + h * 3 + 1];
        const float g2 = g_gates[t * 48 + h * 3 + 2];
        const int obase = (h * TT + t) * DH;
        float4 oc = ((const float4*)(g_outcmp + obase))[dq2];
        float4 os = ((const float4*)(g_outslc + obase))[dq2];
        float4 res;
        res.x = g0 * oc.x + g1 * os.x + g2 * s.x;
        res.y = g0 * oc.y + g1 * os.y + g2 * s.y;
        res.z = g0 * oc.z + g1 * os.z + g2 * s.z;
        res.w = g0 * oc.w + g1 * os.w + g2 * s.w;
        ((float4*)(out + obase))[dq2] = res;
    }
}

// ---------------- launch ----------------
extern "C" void kernel_launch(void* const* d_in, const int* in_sizes, int n_in,
                              void* d_out, int out_size)
{
    (void)in_sizes; (void)n_in; (void)out_size;
    const float* x       = (const float*)d_in[0];
    const float* q       = (const float*)d_in[1];
    const float* gate_w  = (const float*)d_in[2];
    const float* gate_b  = (const float*)d_in[3];
    const float* wk_cmp  = (const float*)d_in[4];
    const float* wv_cmp  = (const float*)d_in[5];
    const float* wk_slc  = (const float*)d_in[6];
    const float* wv_slc  = (const float*)d_in[7];
    const float* wk_win  = (const float*)d_in[8];
    const float* wv_win  = (const float*)d_in[9];
    const float* blockp  = (const float*)d_in[10];
    const float* ck1_w   = (const float*)d_in[11];
    const float* ck1_b   = (const float*)d_in[12];
    const float* ck2_w   = (const float*)d_in[13];
    const float* ck2_b   = (const float*)d_in[14];
    const float* cv1_w   = (const float*)d_in[15];
    const float* cv1_b   = (const float*)d_in[16];
    const float* cv2_w   = (const float*)d_in[17];
    const float* cv2_b   = (const float*)d_in[18];
    float* out = (float*)d_out;

    gemm_all_kernel<<<400, 64>>>(x, gate_w, gate_b,
                                 wk_cmp, wv_cmp, wk_slc, wv_slc, wk_win, wv_win);
    summarize_kernel<<<dim3(NB, 2), 512>>>(blockp,
                                           ck1_w, ck1_b, ck2_w, ck2_b,
                                           cv1_w, cv1_b, cv2_w, cv2_b);
    cmp_kernel<<<dim3(TT, NKV), 128>>>(q);
    slc_kernel<<<dim3(TT, NKV), 256>>>(q);
    win_final_kernel<<<dim3(TT, NKV), 256>>>(q, out);
}